// round 15
// baseline (speedup 1.0000x reference)
#include <cuda_runtime.h>
#include <cuda_fp16.h>
#include <math.h>
#include <stdint.h>

#define DIMC 512
#define NTOK 8192      // B*N
#define SEQ  4096
#define HEADS 8
#define MLPH 2048
#define BH   16

// ============================ scratch buffers ============================
__device__ __align__(256) __half g_hW  [8192ULL*512];    // ln out
__device__ __align__(256) __half g_peH [8192ULL*512];    // pe (fp16)
__device__ __align__(256) __half g_qA  [16ULL*4096*64];  // q (scale*log2e folded) [bh][n][d]
__device__ __align__(256) __half g_kW  [16ULL*4096*64];  // k [bh][n][d]
__device__ __align__(256) __half g_vT  [16ULL*64*4096];  // V transposed [bh][d][n]
__device__ __align__(256) __half g_oW  [8192ULL*512];    // attn out
__device__ __align__(256) float  g_x2f [8192ULL*512];
__device__ __align__(256) __half g_m1W [8192ULL*2048];   // mlp hidden; also hosts peW early
__device__ __align__(256) __half g_qkvB [1536ULL*512];   // weights transposed [N][K]
__device__ __align__(256) __half g_pe2B [512ULL*512];
__device__ __align__(256) __half g_projB[512ULL*512];
__device__ __align__(256) __half g_mlp1B[2048ULL*512];
__device__ __align__(256) __half g_mlp2B[512ULL*2048];

// ============================ helpers ============================
__device__ __forceinline__ uint32_t smem_u32(const void* p){
    uint32_t a;
    asm("{ .reg .u64 t; cvta.to.shared.u64 t, %1; cvt.u32.u64 %0, t; }" : "=r"(a) : "l"(p));
    return a;
}
__device__ __forceinline__ float gelu_f(float v){
    return 0.5f * v * (1.0f + erff(v * 0.70710678118654752440f));
}
__device__ __forceinline__ float fexp2(float x){
    float y;
    asm("ex2.approx.ftz.f32 %0, %1;" : "=f"(y) : "f"(x));
    return y;
}
__device__ __forceinline__ uint32_t packh(float a, float b){
    __half2 t = __floats2half2_rn(a, b);
    return *(uint32_t*)&t;
}
__device__ __forceinline__ void cpasync16(uint32_t dst, const void* src, bool pred){
    asm volatile("cp.async.cg.shared.global [%0], [%1], 16, %2;"
                 :: "r"(dst), "l"(src), "r"(pred ? 16 : 0) : "memory");
}
#define CP_COMMIT()  asm volatile("cp.async.commit_group;" ::: "memory")
#define CP_WAIT(n)   asm volatile("cp.async.wait_group %0;" :: "n"(n) : "memory")

__device__ __forceinline__ void ldm_x4(uint32_t addr, uint32_t& r0, uint32_t& r1,
                                       uint32_t& r2, uint32_t& r3){
    asm volatile("ldmatrix.sync.aligned.m8n8.x4.shared.b16 {%0,%1,%2,%3}, [%4];"
                 : "=r"(r0), "=r"(r1), "=r"(r2), "=r"(r3) : "r"(addr));
}
__device__ __forceinline__ void mma16816(float* c, const uint32_t* a, const uint32_t* b){
    asm volatile("mma.sync.aligned.m16n8k16.row.col.f32.f16.f16.f32 "
                 "{%0,%1,%2,%3}, {%4,%5,%6,%7}, {%8,%9}, {%0,%1,%2,%3};"
                 : "+f"(c[0]), "+f"(c[1]), "+f"(c[2]), "+f"(c[3])
                 : "r"(a[0]), "r"(a[1]), "r"(a[2]), "r"(a[3]), "r"(b[0]), "r"(b[1]));
}

// ============================ GEMM common ============================
#define ROWB 144                 // smem row stride bytes (64 fp16 + 8 pad)
#define TBUF (128 * ROWB)        // 18432 bytes per tile buffer
#define DYN_SMEM (4 * TBUF)      // 73728

__device__ __forceinline__ void load_tile(const __half* __restrict__ G, int ldE,
                                          uint32_t smbase, int tid){
    #pragma unroll
    for (int i = 0; i < 4; i++){
        int id  = tid + i * 256;          // 0..1023
        int r   = id >> 3, c16 = id & 7;
        const char* src = (const char*)(G + (long long)r * ldE) + c16 * 16;
        cpasync16(smbase + r * ROWB + c16 * 16, src, true);
    }
}

// 128x128 tile accumulate over K, BK=64, double buffered
__device__ __forceinline__ void gemm_mainloop(
    const __half* __restrict__ A, const __half* __restrict__ B,
    int Kp, int lda, int ldb, long long m0, long long n0,
    uint32_t smu, int tid, int lane, int wm, int wn, float acc[2][8][4])
{
    uint32_t asb[2] = { smu,        smu + 2 * TBUF };
    uint32_t bsb[2] = { smu + TBUF, smu + 3 * TBUF };
    int nc = Kp >> 6;
    load_tile(A + m0 * lda, lda, asb[0], tid);
    load_tile(B + n0 * ldb, ldb, bsb[0], tid);
    CP_COMMIT();

    for (int c = 0; c < nc; c++){
        int cur = c & 1;
        if (c + 1 < nc){
            load_tile(A + m0 * lda + (c + 1) * 64, lda, asb[cur ^ 1], tid);
            load_tile(B + n0 * ldb + (c + 1) * 64, ldb, bsb[cur ^ 1], tid);
            CP_COMMIT();
            CP_WAIT(1);
        } else {
            CP_WAIT(0);
        }
        __syncthreads();

        #pragma unroll
        for (int kk = 0; kk < 4; kk++){
            uint32_t afr[2][4], bfr[4][4];
            #pragma unroll
            for (int mt = 0; mt < 2; mt++){
                int row = wm + mt * 16 + (lane & 15);
                uint32_t addr = asb[cur] + row * ROWB + kk * 32 + ((lane >> 4) << 4);
                ldm_x4(addr, afr[mt][0], afr[mt][1], afr[mt][2], afr[mt][3]);
            }
            #pragma unroll
            for (int np = 0; np < 4; np++){
                int row = wn + np * 16 + ((lane & 7) | ((lane >> 4) << 3));
                uint32_t addr = bsb[cur] + row * ROWB + kk * 32 + (((lane >> 3) & 1) << 4);
                ldm_x4(addr, bfr[np][0], bfr[np][1], bfr[np][2], bfr[np][3]);
            }
            #pragma unroll
            for (int mt = 0; mt < 2; mt++)
                #pragma unroll
                for (int nt = 0; nt < 8; nt++)
                    mma16816(acc[mt][nt], afr[mt], &bfr[nt >> 1][(nt & 1) * 2]);
        }
        __syncthreads();
    }
}

// ============================ generic GEMM ============================
// C[M,Ntot] = A @ B^T (+bias)(gelu)(+res) -> fp32 C or fp16 Ch (both stride ldc).
__global__ void __launch_bounds__(256, 2) mmagemm(
    const __half* __restrict__ A, const __half* __restrict__ B,
    const float* __restrict__ bias, const float* __restrict__ res,
    float* __restrict__ C, __half* __restrict__ Ch,
    int Kp, int lda, int ldb, int ldc, int epi)
{
    extern __shared__ char dynsm[];
    int tid = threadIdx.x, lane = tid & 31, w = tid >> 5;
    int wm = (w & 3) * 32, wn = (w >> 2) * 64;
    long long m0 = blockIdx.y * 128;
    long long n0 = blockIdx.x * 128;
    uint32_t smu = smem_u32(dynsm);

    float acc[2][8][4];
    #pragma unroll
    for (int i = 0; i < 2; i++)
        #pragma unroll
        for (int j = 0; j < 8; j++)
            #pragma unroll
            for (int q = 0; q < 4; q++) acc[i][j][q] = 0.f;

    gemm_mainloop(A, B, Kp, lda, ldb, m0, n0, smu, tid, lane, wm, wn, acc);

    float* Cs = (float*)dynsm;   // 128 x 132
    #pragma unroll
    for (int mt = 0; mt < 2; mt++)
        #pragma unroll
        for (int nt = 0; nt < 8; nt++){
            int r  = wm + mt * 16 + (lane >> 2);
            int cc = wn + nt * 8 + (lane & 3) * 2;
            Cs[r * 132 + cc]           = acc[mt][nt][0];
            Cs[r * 132 + cc + 1]       = acc[mt][nt][1];
            Cs[(r + 8) * 132 + cc]     = acc[mt][nt][2];
            Cs[(r + 8) * 132 + cc + 1] = acc[mt][nt][3];
        }
    __syncthreads();

    for (int e = tid; e < 128 * 128; e += 256){
        int rr = e >> 7, cc = e & 127;
        int gc = (int)n0 + cc;
        float v = Cs[rr * 132 + cc];
        if (bias)     v += bias[gc];
        if (epi & 1)  v  = gelu_f(v);
        long long ga = (m0 + rr) * ldc + gc;
        if (Ch){
            Ch[ga] = __float2half(v);
        } else {
            if (epi & 2) v += res[ga];
            C[ga] = v;
        }
    }
}

// ============================ QKV GEMM with fused operand-build epilogue ============================
// qkv = hW @ qkvB^T + bias; q(+pe, *0.125*log2e)->qA, k(+pe)->kW, v->vT (transposed).
__global__ void __launch_bounds__(256, 2) qkv_gemm(
    const __half* __restrict__ A, const __half* __restrict__ B,
    const float* __restrict__ bias, const __half* __restrict__ pe,
    __half* __restrict__ qA, __half* __restrict__ kW, __half* __restrict__ vT)
{
    extern __shared__ char dynsm[];
    int tid = threadIdx.x, lane = tid & 31, w = tid >> 5;
    int wm = (w & 3) * 32, wn = (w >> 2) * 64;
    long long m0 = blockIdx.y * 128;
    long long n0 = blockIdx.x * 128;
    uint32_t smu = smem_u32(dynsm);

    float acc[2][8][4];
    #pragma unroll
    for (int i = 0; i < 2; i++)
        #pragma unroll
        for (int j = 0; j < 8; j++)
            #pragma unroll
            for (int q = 0; q < 4; q++) acc[i][j][q] = 0.f;

    gemm_mainloop(A, B, 512, 512, 512, m0, n0, smu, tid, lane, wm, wn, acc);

    float* Cs = (float*)dynsm;   // 128 x 129 (odd stride: conflict-free col reads)
    #pragma unroll
    for (int mt = 0; mt < 2; mt++)
        #pragma unroll
        for (int nt = 0; nt < 8; nt++){
            int r  = wm + mt * 16 + (lane >> 2);
            int cc = wn + nt * 8 + (lane & 3) * 2;
            Cs[r * 129 + cc]           = acc[mt][nt][0];
            Cs[r * 129 + cc + 1]       = acc[mt][nt][1];
            Cs[(r + 8) * 129 + cc]     = acc[mt][nt][2];
            Cs[(r + 8) * 129 + cc + 1] = acc[mt][nt][3];
        }
    __syncthreads();

    int gtype = (int)(n0 >> 9);   // 0 q, 1 k, 2 v
    if (gtype < 2){
        for (int e = tid; e < 128 * 128; e += 256){
            int rr = e >> 7, cc = e & 127;
            int token = (int)m0 + rr;
            int c = ((int)n0 & 511) + cc;
            float val = Cs[rr * 129 + cc] + bias[(int)n0 + cc]
                      + __half2float(pe[(long long)token * 512 + c]);
            int bq = token >> 12, n = token & 4095;
            int h = c >> 6, d = c & 63;
            long long r = ((long long)(bq * 8 + h) * 4096 + n) * 64 + d;
            if (gtype == 0) qA[r] = __float2half(val * 0.18033688011f);  // 0.125*log2(e)
            else            kW[r] = __float2half(val);
        }
    } else {
        for (int e = tid; e < 128 * 128; e += 256){
            int dl = e >> 7, rr = e & 127;          // column-major: coalesced n writes
            int token = (int)m0 + rr;
            int c = ((int)n0 & 511) + dl;
            float val = Cs[rr * 129 + dl] + bias[(int)n0 + dl];
            int bq = token >> 12, n = token & 4095;
            int h = c >> 6, d = c & 63;
            vT[((long long)(bq * 8 + h) * 64 + d) * 4096 + n] = __float2half(val);
        }
    }
}

// ============================ flash attention (base-2 online softmax, lazy l reduction) ============================
// Online max kept (fp16 P operand requires bounded values). Row-sum l is kept as
// per-thread partials (rescale sc is quad-uniform so l = l*sc + local is exact);
// the cross-lane reduction happens ONCE after the loop instead of per chunk.
#define QROWB 144
#define KROWB 144
#define VROWB 144
#define FA_QS   0
#define FA_KV   18432                       // + stage*18432 (K at +0, V at +9216)
#define FA_SMEM (18432 + 3*18432)           // 73728

__device__ __forceinline__ void fa_load_kv(
    const __half* __restrict__ kW, const __half* __restrict__ vT,
    long long kbase, long long vbase, int c, uint32_t smu, int stage, int tid)
{
    uint32_t ks = smu + FA_KV + stage * 18432;
    uint32_t vs = ks + 9216;
    #pragma unroll
    for (int i = 0; i < 2; i++){            // K: 64 rows x 128B
        int id = tid + i * 256;
        int r = id >> 3, c16 = id & 7;
        cpasync16(ks + r * KROWB + c16 * 16,
                  kW + kbase + (long long)(c * 64 + r) * 64 + c16 * 8, true);
    }
    #pragma unroll
    for (int i = 0; i < 2; i++){            // V^T: 64 d-rows x 128B
        int id = tid + i * 256;
        int r = id >> 3, c16 = id & 7;
        cpasync16(vs + r * VROWB + c16 * 16,
                  vT + vbase + (long long)r * 4096 + c * 64 + c16 * 8, true);
    }
}

__global__ void __launch_bounds__(256, 2) flash_attn(
    const __half* __restrict__ qA, const __half* __restrict__ kW,
    const __half* __restrict__ vT, __half* __restrict__ oW)
{
    extern __shared__ char dynsm[];
    uint32_t smu = smem_u32(dynsm);
    int tid = threadIdx.x, lane = tid & 31, w = tid >> 5;
    int bh = blockIdx.y;
    int b = bh >> 3, h = bh & 7;
    int m0 = blockIdx.x * 128;

    long long qbase = ((long long)bh * 4096 + m0) * 64;
    long long kbase = (long long)bh * 4096 * 64;
    long long vbase = (long long)bh * 64 * 4096;

    #pragma unroll
    for (int i = 0; i < 4; i++){            // Q: 128 rows x 128B (group 1)
        int id = tid + i * 256;
        int r = id >> 3, c16 = id & 7;
        cpasync16(smu + FA_QS + r * QROWB + c16 * 16,
                  qA + qbase + (long long)r * 64 + c16 * 8, true);
    }
    CP_COMMIT();
    fa_load_kv(kW, vT, kbase, vbase, 0, smu, 0, tid);   // group 2
    CP_COMMIT();
    fa_load_kv(kW, vT, kbase, vbase, 1, smu, 1, tid);   // group 3
    CP_COMMIT();
    CP_WAIT(2);                             // Q arrived
    __syncthreads();                        // Q visible to all threads

    uint32_t qf[4][4];
    #pragma unroll
    for (int kk = 0; kk < 4; kk++){
        int row = w * 16 + (lane & 15);
        uint32_t addr = smu + FA_QS + row * QROWB + kk * 32 + ((lane >> 4) << 4);
        ldm_x4(addr, qf[kk][0], qf[kk][1], qf[kk][2], qf[kk][3]);
    }

    float O[8][4];
    #pragma unroll
    for (int i = 0; i < 8; i++)
        #pragma unroll
        for (int j = 0; j < 4; j++) O[i][j] = 0.f;
    float m0s = -1e30f, m1s = -1e30f;
    float l0 = 0.f, l1 = 0.f;               // per-thread partials (quad-reduced after loop)

    for (int c = 0; c < 64; c++){
        // wait -> barrier -> issue -> read (single sync per chunk, race-free)
        if (c < 63) CP_WAIT(1);
        else        CP_WAIT(0);
        __syncthreads();
        if (c + 2 < 64){
            fa_load_kv(kW, vT, kbase, vbase, c + 2, smu, (c + 2) % 3, tid);
            CP_COMMIT();
        }

        uint32_t ks = smu + FA_KV + (c % 3) * 18432;
        uint32_t vs = ks + 9216;

        float S[8][4];
        #pragma unroll
        for (int i = 0; i < 8; i++)
            #pragma unroll
            for (int j = 0; j < 4; j++) S[i][j] = 0.f;
        #pragma unroll
        for (int kk = 0; kk < 4; kk++){
            uint32_t bfr[4][4];
            #pragma unroll
            for (int np = 0; np < 4; np++){
                int row = np * 16 + ((lane & 7) | ((lane >> 4) << 3));
                uint32_t addr = ks + row * KROWB + kk * 32 + (((lane >> 3) & 1) << 4);
                ldm_x4(addr, bfr[np][0], bfr[np][1], bfr[np][2], bfr[np][3]);
            }
            #pragma unroll
            for (int nt = 0; nt < 8; nt++)
                mma16816(S[nt], qf[kk], &bfr[nt >> 1][(nt & 1) * 2]);
        }

        // base-2 online softmax; max must be quad-consistent (fp16 P bound)
        float mx0 = -1e30f, mx1 = -1e30f;
        #pragma unroll
        for (int nt = 0; nt < 8; nt++){
            mx0 = fmaxf(mx0, fmaxf(S[nt][0], S[nt][1]));
            mx1 = fmaxf(mx1, fmaxf(S[nt][2], S[nt][3]));
        }
        mx0 = fmaxf(mx0, __shfl_xor_sync(0xffffffffu, mx0, 1));
        mx0 = fmaxf(mx0, __shfl_xor_sync(0xffffffffu, mx0, 2));
        mx1 = fmaxf(mx1, __shfl_xor_sync(0xffffffffu, mx1, 1));
        mx1 = fmaxf(mx1, __shfl_xor_sync(0xffffffffu, mx1, 2));
        float nm0 = fmaxf(m0s, mx0), nm1 = fmaxf(m1s, mx1);
        float sc0 = fexp2(m0s - nm0), sc1 = fexp2(m1s - nm1);
        float sum0 = 0.f, sum1 = 0.f;
        #pragma unroll
        for (int nt = 0; nt < 8; nt++){
            S[nt][0] = fexp2(S[nt][0] - nm0); sum0 += S[nt][0];
            S[nt][1] = fexp2(S[nt][1] - nm0); sum0 += S[nt][1];
            S[nt][2] = fexp2(S[nt][2] - nm1); sum1 += S[nt][2];
            S[nt][3] = fexp2(S[nt][3] - nm1); sum1 += S[nt][3];
        }
        l0 = l0 * sc0 + sum0;               // sc quad-uniform -> partials stay consistent
        l1 = l1 * sc1 + sum1;
        m0s = nm0; m1s = nm1;
        #pragma unroll
        for (int nt = 0; nt < 8; nt++){
            O[nt][0] *= sc0; O[nt][1] *= sc0;
            O[nt][2] *= sc1; O[nt][3] *= sc1;
        }

        #pragma unroll
        for (int kc = 0; kc < 4; kc++){
            uint32_t ph[4];
            int ta = 2 * kc, tb = 2 * kc + 1;
            ph[0] = packh(S[ta][0], S[ta][1]);
            ph[1] = packh(S[ta][2], S[ta][3]);
            ph[2] = packh(S[tb][0], S[tb][1]);
            ph[3] = packh(S[tb][2], S[tb][3]);
            uint32_t vf[4][4];
            #pragma unroll
            for (int np = 0; np < 4; np++){
                int row = np * 16 + ((lane & 7) | ((lane >> 4) << 3));
                uint32_t col = kc * 32 + (((lane >> 3) & 1) << 4);
                ldm_x4(vs + row * VROWB + col, vf[np][0], vf[np][1], vf[np][2], vf[np][3]);
            }
            #pragma unroll
            for (int nt = 0; nt < 8; nt++)
                mma16816(O[nt], ph, &vf[nt >> 1][(nt & 1) * 2]);
        }
    }

    // ---- one cross-lane reduction of row sums, then write O as fp16 ----
    l0 += __shfl_xor_sync(0xffffffffu, l0, 1);
    l0 += __shfl_xor_sync(0xffffffffu, l0, 2);
    l1 += __shfl_xor_sync(0xffffffffu, l1, 1);
    l1 += __shfl_xor_sync(0xffffffffu, l1, 2);
    float inv0 = 1.0f / l0, inv1 = 1.0f / l1;
    int r0 = w * 16 + (lane >> 2);
    int col = (lane & 3) * 2;
    long long tok0 = (long long)b * 4096 + m0 + r0;
    #pragma unroll
    for (int nt = 0; nt < 8; nt++){
        int d = nt * 8 + col;
        __half2 v0 = __floats2half2_rn(O[nt][0] * inv0, O[nt][1] * inv0);
        __half2 v1 = __floats2half2_rn(O[nt][2] * inv1, O[nt][3] * inv1);
        *(__half2*)(oW + tok0 * 512 + h * 64 + d)       = v0;
        *(__half2*)(oW + (tok0 + 8) * 512 + h * 64 + d) = v1;
    }
}

// ============================ LayerNorm -> fp16 (2 rows/CTA, float4) ============================
__global__ void ln_half(const float* __restrict__ x, const float* __restrict__ g,
                        const float* __restrict__ beta, __half* __restrict__ y){
    int tid = threadIdx.x;
    long long row = (long long)blockIdx.x * 2 + (tid >> 7);
    int li = tid & 127;
    const float4* xr = (const float4*)(x + row * DIMC);
    float4 a = xr[li];
    float s  = a.x + a.y + a.z + a.w;
    float ss = a.x*a.x + a.y*a.y + a.z*a.z + a.w*a.w;
    #pragma unroll
    for (int o = 16; o > 0; o >>= 1){
        s  += __shfl_xor_sync(0xffffffffu, s,  o);
        ss += __shfl_xor_sync(0xffffffffu, ss, o);
    }
    __shared__ float s1[8], s2[8];
    int wr = tid >> 5;                      // warps 0-3 row A, 4-7 row B
    if ((tid & 31) == 0){ s1[wr] = s; s2[wr] = ss; }
    __syncthreads();
    int base = (tid >> 7) * 4;
    float tot  = s1[base] + s1[base+1] + s1[base+2] + s1[base+3];
    float tot2 = s2[base] + s2[base+1] + s2[base+2] + s2[base+3];
    float mu  = tot * (1.0f / DIMC);
    float var = tot2 * (1.0f / DIMC) - mu * mu;
    float rsv = rsqrtf(var + 1e-5f);
    float4 gg = ((const float4*)g)[li];
    float4 bb = ((const float4*)beta)[li];
    __half2 h0 = __floats2half2_rn((a.x - mu) * rsv * gg.x + bb.x,
                                   (a.y - mu) * rsv * gg.y + bb.y);
    __half2 h1 = __floats2half2_rn((a.z - mu) * rsv * gg.z + bb.z,
                                   (a.w - mu) * rsv * gg.w + bb.w);
    __half2* yr = (__half2*)(y + row * DIMC);
    yr[li * 2]     = h0;
    yr[li * 2 + 1] = h1;
}

// ============================ merged weight transpose -> fp16 [N][K] ============================
// Segments (32x32 tiles): qkv 768 | pe2 256 | proj 256 | mlp1 1024 | mlp2 1024 = 3328
__global__ void thalf_all(const float* __restrict__ W0, const float* __restrict__ W1,
                          const float* __restrict__ W2, const float* __restrict__ W3,
                          const float* __restrict__ W4,
                          __half* __restrict__ O0, __half* __restrict__ O1,
                          __half* __restrict__ O2, __half* __restrict__ O3,
                          __half* __restrict__ O4){
    __shared__ float tile[32][33];
    int t = blockIdx.x;
    const float* W; __half* O; int K, N, base;
    if      (t <  768){ W = W0; O = O0; K = 512;  N = 1536; base = 0;    }
    else if (t < 1024){ W = W1; O = O1; K = 512;  N = 512;  base = 768;  }
    else if (t < 1280){ W = W2; O = O2; K = 512;  N = 512;  base = 1024; }
    else if (t < 2304){ W = W3; O = O3; K = 512;  N = 2048; base = 1280; }
    else              { W = W4; O = O4; K = 2048; N = 512;  base = 2304; }
    int lt = t - base;
    int nx = N >> 5;
    int k0 = (lt / nx) * 32, n0 = (lt % nx) * 32;
    int tx = threadIdx.x, ty = threadIdx.y;
    #pragma unroll
    for (int j = 0; j < 4; j++)
        tile[ty + j * 8][tx] = W[(long long)(k0 + ty + j * 8) * N + n0 + tx];
    __syncthreads();
    #pragma unroll
    for (int j = 0; j < 4; j++){
        int n = n0 + ty + j * 8;
        O[(long long)n * K + k0 + tx] = __float2half(tile[tx][ty + j * 8]);
    }
}

// ============================ PE layer 1 -> fp16 ============================
__global__ void pe1_half(const float* __restrict__ pos, const float* __restrict__ w1,
                         const float* __restrict__ b1, __half* __restrict__ out){
    long long idx = (long long)blockIdx.x * 256 + threadIdx.x;   // 8192*512
    int m = (int)(idx >> 9), c = (int)(idx & 511);
    float p0 = pos[m * 3], p1 = pos[m * 3 + 1], p2 = pos[m * 3 + 2];
    float v = gelu_f(p0 * w1[c] + p1 * w1[512 + c] + p2 * w1[1024 + c] + b1[c]);
    out[idx] = __float2half(v);
}

// ============================ host ============================
extern "C" void kernel_launch(void* const* d_in, const int* in_sizes, int n_in,
                              void* d_out, int out_size){
    const float* x      = (const float*)d_in[0];
    const float* pos    = (const float*)d_in[1];
    const float* qkv_w  = (const float*)d_in[2];
    const float* qkv_b  = (const float*)d_in[3];
    const float* proj_w = (const float*)d_in[4];
    const float* proj_b = (const float*)d_in[5];
    const float* pe_w1  = (const float*)d_in[6];
    const float* pe_b1  = (const float*)d_in[7];
    const float* pe_w2  = (const float*)d_in[8];
    const float* pe_b2  = (const float*)d_in[9];
    const float* mlp_w1 = (const float*)d_in[10];
    const float* mlp_b1 = (const float*)d_in[11];
    const float* mlp_w2 = (const float*)d_in[12];
    const float* mlp_b2 = (const float*)d_in[13];
    const float* n1_g   = (const float*)d_in[14];
    const float* n1_b   = (const float*)d_in[15];
    const float* n2_g   = (const float*)d_in[16];
    const float* n2_b   = (const float*)d_in[17];
    float* out = (float*)d_out;

    __half *hW, *peH, *qA, *kW, *vT, *oW, *m1W;
    __half *qkvB, *pe2B, *projB, *mlp1B, *mlp2B;
    float *x2f;
    cudaGetSymbolAddress((void**)&hW,   g_hW);
    cudaGetSymbolAddress((void**)&peH,  g_peH);
    cudaGetSymbolAddress((void**)&qA,   g_qA);
    cudaGetSymbolAddress((void**)&kW,   g_kW);
    cudaGetSymbolAddress((void**)&vT,   g_vT);
    cudaGetSymbolAddress((void**)&oW,   g_oW);
    cudaGetSymbolAddress((void**)&x2f,  g_x2f);
    cudaGetSymbolAddress((void**)&m1W,  g_m1W);
    cudaGetSymbolAddress((void**)&qkvB, g_qkvB);
    cudaGetSymbolAddress((void**)&pe2B, g_pe2B);
    cudaGetSymbolAddress((void**)&projB,g_projB);
    cudaGetSymbolAddress((void**)&mlp1B,g_mlp1B);
    cudaGetSymbolAddress((void**)&mlp2B,g_mlp2B);

    __half* peW = m1W;   // disjoint lifetime

    cudaFuncSetAttribute(mmagemm,    cudaFuncAttributeMaxDynamicSharedMemorySize, DYN_SMEM);
    cudaFuncSetAttribute(qkv_gemm,   cudaFuncAttributeMaxDynamicSharedMemorySize, DYN_SMEM);
    cudaFuncSetAttribute(flash_attn, cudaFuncAttributeMaxDynamicSharedMemorySize, FA_SMEM);

    dim3 tsb(32, 8);

    // all weight transposes in one launch
    thalf_all<<<3328, tsb>>>(qkv_w, pe_w2, proj_w, mlp_w1, mlp_w2,
                             qkvB, pe2B, projB, mlp1B, mlp2B);

    // 1. peW = fp16(gelu(pos @ pe_w1 + pe_b1)); peH = fp16(peW @ pe2B^T + pe_b2)
    pe1_half<<<(NTOK*DIMC)/256, 256>>>(pos, pe_w1, pe_b1, peW);
    mmagemm<<<dim3(4, 64, 1), 256, DYN_SMEM>>>(
        peW, pe2B, pe_b2, nullptr, nullptr, peH,
        512, 512, 512, 512, 0);

    // 2. hW = fp16(LN1(x))
    ln_half<<<NTOK/2, 256>>>(x, n1_g, n1_b, hW);

    // 3. qkv GEMM with fused operand construction
    qkv_gemm<<<dim3(12, 64, 1), 256, DYN_SMEM>>>(
        hW, qkvB, qkv_b, peH, qA, kW, vT);

    // 4. fused flash attention -> oW (fp16)
    flash_attn<<<dim3(32, 16), 256, FA_SMEM>>>(qA, kW, vT, oW);

    // 5. x2 = x + oW @ projB^T + proj_b
    mmagemm<<<dim3(4, 64, 1), 256, DYN_SMEM>>>(
        oW, projB, proj_b, x, x2f, nullptr,
        512, 512, 512, 512, 2);

    // 6. hW = fp16(LN2(x2))
    ln_half<<<NTOK/2, 256>>>(x2f, n2_g, n2_b, hW);

    // 7. m1W = fp16(gelu(hW @ mlp1B^T + mlp_b1))
    mmagemm<<<dim3(16, 64, 1), 256, DYN_SMEM>>>(
        hW, mlp1B, mlp_b1, nullptr, nullptr, m1W,
        512, 512, 512, 2048, 1);

    // 8. out = x2 + m1W @ mlp2B^T + mlp_b2
    mmagemm<<<dim3(4, 64, 1), 256, DYN_SMEM>>>(
        m1W, mlp2B, mlp_b2, x2f, out, nullptr,
        2048, 2048, 2048, 512, 2);
}